// round 14
// baseline (speedup 1.0000x reference)
#include <cuda_runtime.h>
#include <cstdint>

#define Bn   16
#define Tn   512
#define INn  128
#define Hn   256
#define Dn   8
#define EPSf 1e-5f

#define CL        4            // CTAs per cluster (4-way k/row split) — measured optimum
#define SCAN_CTAS 64           // 16 batches x 4 CTAs
#define GRID_SCAN 256          // 64 scan CTAs + 192 zero-fill CTAs

// ---------------- scratch (static device arrays; no allocation) ----------------
__device__ float g_xproj[Bn * Tn * Hn];          // 8 MB
__device__ float g_bd   [Bn * Tn * 2 * Dn];      // 512 KB
__device__ float g_hp   [Bn * Tn * CL * 24];     // 3 MB: per-rank head partials

// ---------------- helpers ----------------
__device__ __forceinline__ uint32_t smem_u32(const void* p) {
    uint32_t a;
    asm("{ .reg .u64 t; cvta.to.shared.u64 t, %1; cvt.u32.u64 %0, t; }"
        : "=r"(a) : "l"(p));
    return a;
}

__device__ __forceinline__ uint32_t cluster_rank() {
    uint32_t r;
    asm("mov.u32 %0, %%cluster_ctarank;" : "=r"(r));
    return r;
}

__device__ __forceinline__ uint32_t mapa_u32(uint32_t local_addr, uint32_t rank) {
    uint32_t r;
    asm("mapa.shared::cluster.u32 %0, %1, %2;" : "=r"(r) : "r"(local_addr), "r"(rank));
    return r;
}

__device__ __forceinline__ unsigned long long pack2(float x, float y) {
    unsigned long long r;
    asm("mov.b64 %0, {%1, %2};" : "=l"(r) : "f"(x), "f"(y));
    return r;
}
__device__ __forceinline__ void unpack2(unsigned long long v, float& x, float& y) {
    asm("mov.b64 {%0, %1}, %2;" : "=f"(x), "=f"(y) : "l"(v));
}
// packed fp32x2 FMA (Blackwell FFMA2): 2 fp32 MACs per instruction
__device__ __forceinline__ void ffma2(unsigned long long& d,
                                      unsigned long long a,
                                      unsigned long long b) {
    asm("fma.rn.f32x2 %0, %1, %2, %3;" : "=l"(d) : "l"(a), "l"(b), "l"(d));
}

__device__ __forceinline__ float tanh_approx(float x) {
    float r;
    asm("tanh.approx.f32 %0, %1;" : "=f"(r) : "f"(x));
    return r;
}

__device__ __forceinline__ void mbar_init(uint32_t addr, uint32_t count) {
    asm volatile("mbarrier.init.shared.b64 [%0], %1;" :: "r"(addr), "r"(count) : "memory");
}

__device__ __forceinline__ void mbar_arrive_expect_tx(uint32_t addr, uint32_t bytes) {
    asm volatile("mbarrier.arrive.expect_tx.shared.b64 _, [%0], %1;"
                 :: "r"(addr), "r"(bytes) : "memory");
}

__device__ __forceinline__ void mbar_wait(uint32_t addr, int phase) {
    asm volatile(
        "{\n\t"
        ".reg .pred P1;\n\t"
        "LAB_%=:\n\t"
        "mbarrier.try_wait.parity.acquire.cta.shared::cta.b64 P1, [%0], %1, 0x989680;\n\t"
        "@P1 bra DONE_%=;\n\t"
        "bra LAB_%=;\n\t"
        "DONE_%=:\n\t"
        "}"
        :: "r"(addr), "r"(phase) : "memory");
}

// async remote smem store (b32) with tx-completion on the remote mbarrier
__device__ __forceinline__ void st_async_f32(uint32_t raddr, float v, uint32_t rmbar) {
    asm volatile(
        "st.async.shared::cluster.mbarrier::complete_tx::bytes.b32 [%0], %1, [%2];"
        :: "r"(raddr), "r"(__float_as_uint(v)), "r"(rmbar) : "memory");
}

// named barriers (asymmetric producer/consumer)
__device__ __forceinline__ void bar_sync(int id, int cnt) {
    asm volatile("bar.sync %0, %1;" :: "r"(id), "r"(cnt) : "memory");
}
__device__ __forceinline__ void bar_arrive(int id, int cnt) {
    asm volatile("bar.arrive %0, %1;" :: "r"(id), "r"(cnt) : "memory");
}

// ---------------- kernel 1: x_proj = y @ W_ih^T + b_ih ----------------
__global__ void k_xproj(const float* __restrict__ y,
                        const float* __restrict__ W_ih,
                        const float* __restrict__ b_ih) {
    const int h  = threadIdx.x;       // 0..255
    const int b  = blockIdx.y;
    const int t0 = blockIdx.x * 4;

    const float4* Wr = reinterpret_cast<const float4*>(W_ih + h * INn);
    const float4* Y  = reinterpret_cast<const float4*>(y + ((size_t)b * Tn + t0) * INn);

    float a0 = 0.f, a1 = 0.f, a2 = 0.f, a3 = 0.f;
#pragma unroll 4
    for (int k = 0; k < 32; k++) {
        float4 wv = __ldg(Wr + k);
        float4 y0 = __ldg(Y + k);
        float4 y1 = __ldg(Y + 32 + k);
        float4 y2 = __ldg(Y + 64 + k);
        float4 y3 = __ldg(Y + 96 + k);
        a0 += wv.x * y0.x + wv.y * y0.y + wv.z * y0.z + wv.w * y0.w;
        a1 += wv.x * y1.x + wv.y * y1.y + wv.z * y1.z + wv.w * y1.w;
        a2 += wv.x * y2.x + wv.y * y2.y + wv.z * y2.z + wv.w * y2.w;
        a3 += wv.x * y3.x + wv.y * y3.y + wv.z * y3.z + wv.w * y3.w;
    }
    const float bias = __ldg(b_ih + h);
    size_t base = ((size_t)b * Tn + t0) * Hn + h;
    g_xproj[base]          = a0 + bias;
    g_xproj[base + Hn]     = a1 + bias;
    g_xproj[base + 2 * Hn] = a2 + bias;
    g_xproj[base + 3 * Hn] = a3 + bias;
}

// ---------------- kernel 2: RNN scan (CL=4, asymmetric bars) + heads + zero-fill ----------------
// Owners (64 threads owning this CTA's rows) never block at a CTA barrier:
// they wait only on the mbar, finalize, STS h, bar.arrive(1). A private
// bar.sync(2,64) orders their own STS->LDS. Shippers bar.sync(1,256) on the
// owners' h publication. ps_in is [row][rank] so owners read all 4 partials
// with a single LDS.128.
__global__ void __cluster_dims__(CL, 1, 1) __launch_bounds__(256, 1)
k_scan(const float* __restrict__ W_hh, const float* __restrict__ b_hh,
       const float* __restrict__ W_mean, const float* __restrict__ W_bd,
       float* __restrict__ prec) {
    // ---- zero-fill CTAs ----
    if (blockIdx.x >= SCAN_CTAS) {
        const long long total = (long long)Bn * Dn * Tn * Tn / 4;   // float4 count
        const int nz = GRID_SCAN - SCAN_CTAS;
        long long i = (long long)(blockIdx.x - SCAN_CTAS) * blockDim.x + threadIdx.x;
        const long long stride = (long long)nz * blockDim.x;
        const float4 z = make_float4(0.f, 0.f, 0.f, 0.f);
        for (; i < total; i += stride)
            __stcs(reinterpret_cast<float4*>(prec) + i, z);
        return;
    }

    __shared__ __align__(16) float hbuf[2][64];        // this CTA's OWNED h slice
    __shared__ __align__(16) float ps_in[2][64][CL];   // [row][source rank] -> LDS.128
    __shared__ __align__(8) unsigned long long mbar[2];

    const int tid = threadIdx.x;                 // = global output row
    const unsigned rank = cluster_rank();        // 0..3
    const int batch = blockIdx.x >> 2;
    const unsigned owner = (unsigned)tid >> 6;   // owner CTA of this row
    const bool own = (owner == rank);
    const int lrow = tid & 63;

    // register-resident weights: W_hh[tid, rank*64 .. +64)  (32 f32x2)
    unsigned long long w[32];
    {
        const float2* wr = reinterpret_cast<const float2*>(W_hh + (size_t)tid * Hn + (rank << 6));
#pragma unroll
        for (int i = 0; i < 32; i++) {
            float2 v = __ldg(wr + i);
            w[i] = pack2(v.x, v.y);
        }
    }
    const float bias = own ? __ldg(b_hh + tid) : 0.f;
    const float* xcol = g_xproj + (size_t)batch * Tn * Hn + tid;

    // ---- head-partial worker setup (96 shipper threads per CTA) ----
    const int sid = (tid >= (int)((rank << 6) + 64)) ? tid - 64 : tid;
    const bool worker = (!own) && (sid < 96);    // warp-aligned cutoff
    const int ho = sid >> 2;                     // head output 0..23 (8 mean + 16 bd)
    const int hq = sid & 3;                      // 16-wide k sub-quarter
    unsigned long long wh[8];
    if (worker) {
        const float* whrow = (ho < Dn ? W_mean + ho * Hn : W_bd + (ho - Dn) * Hn)
                             + (rank << 6) + (hq << 4);
        const float2* wh2 = reinterpret_cast<const float2*>(whrow);
#pragma unroll
        for (int i = 0; i < 8; i++) {
            float2 v = __ldg(wh2 + i);
            wh[i] = pack2(v.x, v.y);
        }
    }
    float* hp_base = g_hp + ((size_t)batch * Tn * CL + rank) * 24 + ho;

    if (tid == 0) { mbar_init(smem_u32(&mbar[0]), 1); mbar_init(smem_u32(&mbar[1]), 1); }
    if (tid < 64) { hbuf[0][tid] = 0.f; }                       // h(-1) = 0
    for (int i = tid; i < 2 * 64 * CL; i += 256)                // zero ps_in (own slot stays 0)
        reinterpret_cast<float*>(ps_in)[i] = 0.f;
    __syncthreads();
    asm volatile("barrier.cluster.arrive.aligned;" ::: "memory");
    asm volatile("barrier.cluster.wait.aligned;" ::: "memory");

    // remote targets for shippers: slot [buf][lrow][my_rank] in owner CTA
    uint32_t r_ps[2] = {0, 0}, r_mbar[2] = {0, 0};
    if (!own) {
        r_ps[0]   = mapa_u32(smem_u32(&ps_in[0][lrow][rank]), owner);
        r_ps[1]   = mapa_u32(smem_u32(&ps_in[1][lrow][rank]), owner);
        r_mbar[0] = mapa_u32(smem_u32(&mbar[0]), owner);
        r_mbar[1] = mapa_u32(smem_u32(&mbar[1]), owner);
    }
    const uint32_t l_mbar[2] = { smem_u32(&mbar[0]), smem_u32(&mbar[1]) };

    int ph[2] = {0, 0};
    float xv = own ? (__ldg(xcol) + bias) : 0.f;   // x(0)+b_hh, bias pre-folded

    for (int t = 0; t < Tn; ++t) {
        const int buf = t & 1;
        const int nb  = buf ^ 1;

        if (t > 0 && !own) bar_sync(1, 256);   // wait for owners' h(t-1) publication

        // prefetch next x (+bias) — off critical path
        float xnext = 0.f;
        if (own && (t + 1) < Tn) xnext = __ldg(xcol + (size_t)(t + 1) * Hn) + bias;

        // expect 3 sources x 64 rows x 4 B
        if (tid == 0) mbar_arrive_expect_tx(l_mbar[buf], 768);

        // 64-wide dot over owned h slice (32 FFMA2)
        const ulonglong2* hp = reinterpret_cast<const ulonglong2*>(hbuf[buf]);
        unsigned long long acc0 = 0ull, acc1 = 0ull;
#pragma unroll
        for (int i = 0; i < 16; i++) {
            ulonglong2 hv = hp[i];
            ffma2(acc0, w[2 * i],     hv.x);
            ffma2(acc1, w[2 * i + 1], hv.y);
        }
        float a0, a1, c0, c1;
        unpack2(acc0, a0, a1);
        unpack2(acc1, c0, c1);
        const float part = (a0 + c0) + (a1 + c1);

        if (!own) {
            // ship partial to the row's owner FIRST; drains in background
            st_async_f32(r_ps[buf], part, r_mbar[buf]);

            // head partials for h(t-1) — hidden under the owners' wait
            if (worker && t > 0) {
                const ulonglong2* hh = reinterpret_cast<const ulonglong2*>(&hbuf[buf][hq << 4]);
                unsigned long long b0 = 0ull, b1 = 0ull;
#pragma unroll
                for (int i = 0; i < 4; i++) {
                    ulonglong2 hv = hh[i];
                    ffma2(b0, wh[2 * i],     hv.x);
                    ffma2(b1, wh[2 * i + 1], hv.y);
                }
                float p0, p1, p2, p3;
                unpack2(b0, p0, p1);
                unpack2(b1, p2, p3);
                float hpv = (p0 + p2) + (p1 + p3);
                hpv += __shfl_xor_sync(0xffffffffu, hpv, 1);
                hpv += __shfl_xor_sync(0xffffffffu, hpv, 2);
                if (hq == 0) hp_base[(size_t)(t - 1) * (CL * 24)] = hpv;
            }
        } else {
            mbar_wait(l_mbar[buf], ph[buf]);
            ph[buf] ^= 1;
            // single LDS.128: all 4 source partials (own slot permanently 0)
            float4 pv = *reinterpret_cast<const float4*>(&ps_in[buf][lrow][0]);
            float s = part + xv + ((pv.x + pv.y) + (pv.z + pv.w));
            float hn = tanh_approx(s);
            xv = xnext;
            hbuf[nb][lrow] = hn;                // publish h(t)
            bar_arrive(1, 256);                 // release shippers (non-blocking)
            bar_sync(2, 64);                    // owners-only: order STS -> next LDS
        }
    }

    // final head partials for h(511): shippers must see owners' last STS
    if (!own) bar_sync(1, 256);
    if (worker) {
        const ulonglong2* hh = reinterpret_cast<const ulonglong2*>(&hbuf[0][hq << 4]);
        unsigned long long b0 = 0ull, b1 = 0ull;
#pragma unroll
        for (int i = 0; i < 4; i++) {
            ulonglong2 hv = hh[i];
            ffma2(b0, wh[2 * i],     hv.x);
            ffma2(b1, wh[2 * i + 1], hv.y);
        }
        float p0, p1, p2, p3;
        unpack2(b0, p0, p1);
        unpack2(b1, p2, p3);
        float hpv = (p0 + p2) + (p1 + p3);
        hpv += __shfl_xor_sync(0xffffffffu, hpv, 1);
        hpv += __shfl_xor_sync(0xffffffffu, hpv, 2);
        if (hq == 0) hp_base[(size_t)(Tn - 1) * (CL * 24)] = hpv;
    }

    // keep smem/barriers alive until peers' in-flight st.asyncs complete
    asm volatile("barrier.cluster.arrive.aligned;" ::: "memory");
    asm volatile("barrier.cluster.wait.aligned;" ::: "memory");
}

// ---------------- kernel 3: reduce head partials (4 ranks) + bias ----------------
__global__ void __launch_bounds__(256) k_heads(const float* __restrict__ b_mean,
                                               const float* __restrict__ b_bd,
                                               float* __restrict__ out_mean) {
    const int idx = blockIdx.x * 256 + threadIdx.x;   // 0 .. Bn*Tn*24-1
    const int o  = idx % 24;
    const int bt = idx / 24;

    const float* p = g_hp + (size_t)bt * (CL * 24) + o;
    float s = (p[0] + p[24]) + (p[48] + p[72]);
    if (o < Dn) out_mean[(size_t)bt * Dn + o] = s + __ldg(b_mean + o);
    else        g_bd[(size_t)bt * (2 * Dn) + (o - Dn)] = s + __ldg(b_bd + (o - Dn));
}

// ---------------- kernel 4: tridiagonal writes only (zeros done in k_scan) ----------------
__global__ void __launch_bounds__(256) k_prec_diag(float* __restrict__ prec) {
    const int idx = blockIdx.x * 256 + threadIdx.x;   // 0 .. 65535 = (b*8+d)*512 + i
    const int i   = idx & 511;
    const int bd_ = idx >> 9;
    const int d   = bd_ & 7;
    const int b   = bd_ >> 3;

    const size_t row = ((size_t)b * Tn + i) * 16;
    float diag_i = g_bd[row + d];
    float off_i  = g_bd[row + 8 + d];
    float off_p  = 0.f;
    if (i > 0) off_p = g_bd[row - 16 + 8 + d];

    float mainv  = diag_i * diag_i + off_p * off_p + EPSf;
    float supd_r = diag_i * off_i;   // supd[i] (columns i/i+1)

    float* base = prec + ((size_t)bd_ * Tn + i) * Tn + i;   // [b,d,i,i]
    base[0] = mainv;
    if (i < Tn - 1) {
        base[1]  = supd_r;    // [i, i+1]
        base[Tn] = supd_r;    // [i+1, i]
    }
}

// ---------------- launch ----------------
extern "C" void kernel_launch(void* const* d_in, const int* in_sizes, int n_in,
                              void* d_out, int out_size) {
    const float* y      = (const float*)d_in[0];
    const float* W_ih   = (const float*)d_in[1];
    const float* W_hh   = (const float*)d_in[2];
    const float* b_ih   = (const float*)d_in[3];
    const float* b_hh   = (const float*)d_in[4];
    const float* W_mean = (const float*)d_in[5];
    const float* b_mean = (const float*)d_in[6];
    const float* W_bd   = (const float*)d_in[7];
    const float* b_bd   = (const float*)d_in[8];
    float* out = (float*)d_out;
    float* prec = out + Bn * Tn * Dn;

    k_xproj<<<dim3(Tn / 4, Bn), 256>>>(y, W_ih, b_ih);
    k_scan<<<GRID_SCAN, 256>>>(W_hh, b_hh, W_mean, W_bd, prec);  // scan + heads + zero-fill
    k_heads<<<(Bn * Tn * 24) / 256, 256>>>(b_mean, b_bd, out);
    k_prec_diag<<<(Bn * Dn * Tn) / 256, 256>>>(prec);
}

// round 15
// speedup vs baseline: 1.0795x; 1.0795x over previous
#include <cuda_runtime.h>
#include <cstdint>

#define Bn   16
#define Tn   512
#define INn  128
#define Hn   256
#define Dn   8
#define EPSf 1e-5f

#define CL        4            // CTAs per cluster (4-way k/row split) — measured optimum
#define SCAN_CTAS 64           // 16 batches x 4 CTAs
#define GRID_SCAN 256          // 64 scan CTAs + 192 zero-fill CTAs

// ---------------- scratch (static device arrays; no allocation) ----------------
__device__ float g_xproj[Bn * Tn * Hn];          // 8 MB
__device__ float g_hp   [Bn * Tn * CL * 24];     // 3 MB: per-rank head partials

// ---------------- helpers ----------------
__device__ __forceinline__ uint32_t smem_u32(const void* p) {
    uint32_t a;
    asm("{ .reg .u64 t; cvta.to.shared.u64 t, %1; cvt.u32.u64 %0, t; }"
        : "=r"(a) : "l"(p));
    return a;
}

__device__ __forceinline__ uint32_t cluster_rank() {
    uint32_t r;
    asm("mov.u32 %0, %%cluster_ctarank;" : "=r"(r));
    return r;
}

__device__ __forceinline__ uint32_t mapa_u32(uint32_t local_addr, uint32_t rank) {
    uint32_t r;
    asm("mapa.shared::cluster.u32 %0, %1, %2;" : "=r"(r) : "r"(local_addr), "r"(rank));
    return r;
}

__device__ __forceinline__ unsigned long long pack2(float x, float y) {
    unsigned long long r;
    asm("mov.b64 %0, {%1, %2};" : "=l"(r) : "f"(x), "f"(y));
    return r;
}
__device__ __forceinline__ void unpack2(unsigned long long v, float& x, float& y) {
    asm("mov.b64 {%0, %1}, %2;" : "=f"(x), "=f"(y) : "l"(v));
}
// packed fp32x2 FMA (Blackwell FFMA2): 2 fp32 MACs per instruction
__device__ __forceinline__ void ffma2(unsigned long long& d,
                                      unsigned long long a,
                                      unsigned long long b) {
    asm("fma.rn.f32x2 %0, %1, %2, %3;" : "=l"(d) : "l"(a), "l"(b), "l"(d));
}

__device__ __forceinline__ float tanh_approx(float x) {
    float r;
    asm("tanh.approx.f32 %0, %1;" : "=f"(r) : "f"(x));
    return r;
}

__device__ __forceinline__ void mbar_init(uint32_t addr, uint32_t count) {
    asm volatile("mbarrier.init.shared.b64 [%0], %1;" :: "r"(addr), "r"(count) : "memory");
}

__device__ __forceinline__ void mbar_arrive_expect_tx(uint32_t addr, uint32_t bytes) {
    asm volatile("mbarrier.arrive.expect_tx.shared.b64 _, [%0], %1;"
                 :: "r"(addr), "r"(bytes) : "memory");
}

__device__ __forceinline__ void mbar_wait(uint32_t addr, int phase) {
    asm volatile(
        "{\n\t"
        ".reg .pred P1;\n\t"
        "LAB_%=:\n\t"
        "mbarrier.try_wait.parity.acquire.cta.shared::cta.b64 P1, [%0], %1, 0x989680;\n\t"
        "@P1 bra DONE_%=;\n\t"
        "bra LAB_%=;\n\t"
        "DONE_%=:\n\t"
        "}"
        :: "r"(addr), "r"(phase) : "memory");
}

// async remote smem store (b32) with tx-completion on the remote mbarrier
__device__ __forceinline__ void st_async_f32(uint32_t raddr, float v, uint32_t rmbar) {
    asm volatile(
        "st.async.shared::cluster.mbarrier::complete_tx::bytes.b32 [%0], %1, [%2];"
        :: "r"(raddr), "r"(__float_as_uint(v)), "r"(rmbar) : "memory");
}

// ---------------- kernel 1: x_proj = y @ W_ih^T + b_ih ----------------
__global__ void k_xproj(const float* __restrict__ y,
                        const float* __restrict__ W_ih,
                        const float* __restrict__ b_ih) {
    const int h  = threadIdx.x;       // 0..255
    const int b  = blockIdx.y;
    const int t0 = blockIdx.x * 4;

    const float4* Wr = reinterpret_cast<const float4*>(W_ih + h * INn);
    const float4* Y  = reinterpret_cast<const float4*>(y + ((size_t)b * Tn + t0) * INn);

    float a0 = 0.f, a1 = 0.f, a2 = 0.f, a3 = 0.f;
#pragma unroll 4
    for (int k = 0; k < 32; k++) {
        float4 wv = __ldg(Wr + k);
        float4 y0 = __ldg(Y + k);
        float4 y1 = __ldg(Y + 32 + k);
        float4 y2 = __ldg(Y + 64 + k);
        float4 y3 = __ldg(Y + 96 + k);
        a0 += wv.x * y0.x + wv.y * y0.y + wv.z * y0.z + wv.w * y0.w;
        a1 += wv.x * y1.x + wv.y * y1.y + wv.z * y1.z + wv.w * y1.w;
        a2 += wv.x * y2.x + wv.y * y2.y + wv.z * y2.z + wv.w * y2.w;
        a3 += wv.x * y3.x + wv.y * y3.y + wv.z * y3.z + wv.w * y3.w;
    }
    const float bias = __ldg(b_ih + h);
    size_t base = ((size_t)b * Tn + t0) * Hn + h;
    g_xproj[base]          = a0 + bias;
    g_xproj[base + Hn]     = a1 + bias;
    g_xproj[base + 2 * Hn] = a2 + bias;
    g_xproj[base + 3 * Hn] = a3 + bias;
}

// ---------------- kernel 2: RNN scan (CL=4) + in-scan head partials + prec zero-fill ----------------
// EXACT R13 structure (best measured); only change: b_hh folded into xv prefetch.
__global__ void __cluster_dims__(CL, 1, 1) __launch_bounds__(256, 1)
k_scan(const float* __restrict__ W_hh, const float* __restrict__ b_hh,
       const float* __restrict__ W_mean, const float* __restrict__ W_bd,
       float* __restrict__ prec) {
    // ---- zero-fill CTAs ----
    if (blockIdx.x >= SCAN_CTAS) {
        const long long total = (long long)Bn * Dn * Tn * Tn / 4;   // float4 count
        const int nz = GRID_SCAN - SCAN_CTAS;
        long long i = (long long)(blockIdx.x - SCAN_CTAS) * blockDim.x + threadIdx.x;
        const long long stride = (long long)nz * blockDim.x;
        const float4 z = make_float4(0.f, 0.f, 0.f, 0.f);
        for (; i < total; i += stride)
            __stcs(reinterpret_cast<float4*>(prec) + i, z);
        return;
    }

    __shared__ __align__(16) float hbuf[2][64];      // this CTA's OWNED h slice
    __shared__ __align__(16) float ps_in[2][CL][64]; // incoming partials by source rank
    __shared__ __align__(8) unsigned long long mbar[2];

    const int tid = threadIdx.x;                 // = global output row
    const unsigned rank = cluster_rank();        // 0..3
    const int batch = blockIdx.x >> 2;
    const unsigned owner = (unsigned)tid >> 6;   // owner CTA of this row
    const bool own = (owner == rank);
    const int lrow = tid & 63;

    // register-resident weights: W_hh[tid, rank*64 .. +64)  (32 f32x2)
    unsigned long long w[32];
    {
        const float2* wr = reinterpret_cast<const float2*>(W_hh + (size_t)tid * Hn + (rank << 6));
#pragma unroll
        for (int i = 0; i < 32; i++) {
            float2 v = __ldg(wr + i);
            w[i] = pack2(v.x, v.y);
        }
    }
    const float bias = own ? __ldg(b_hh + tid) : 0.f;
    const float* xcol = g_xproj + (size_t)batch * Tn * Hn + tid;

    // ---- head-partial worker setup (96 shipper threads per CTA) ----
    const int sid = (tid >= (int)((rank << 6) + 64)) ? tid - 64 : tid;
    const bool worker = (!own) && (sid < 96);    // warp-aligned cutoff
    const int ho = sid >> 2;                     // head output 0..23 (8 mean + 16 bd)
    const int hq = sid & 3;                      // 16-wide k sub-quarter
    unsigned long long wh[8];
    if (worker) {
        const float* whrow = (ho < Dn ? W_mean + ho * Hn : W_bd + (ho - Dn) * Hn)
                             + (rank << 6) + (hq << 4);
        const float2* wh2 = reinterpret_cast<const float2*>(whrow);
#pragma unroll
        for (int i = 0; i < 8; i++) {
            float2 v = __ldg(wh2 + i);
            wh[i] = pack2(v.x, v.y);
        }
    }
    float* hp_base = g_hp + ((size_t)batch * Tn * CL + rank) * 24 + ho;

    if (tid == 0) { mbar_init(smem_u32(&mbar[0]), 1); mbar_init(smem_u32(&mbar[1]), 1); }
    if (tid < 64) { hbuf[0][tid] = 0.f; }                       // h(-1) = 0
    for (int i = tid; i < 2 * CL * 64; i += 256)                // zero ps_in (own slot stays 0)
        reinterpret_cast<float*>(ps_in)[i] = 0.f;
    __syncthreads();
    asm volatile("barrier.cluster.arrive.aligned;" ::: "memory");
    asm volatile("barrier.cluster.wait.aligned;" ::: "memory");

    // remote targets for shippers: slot [buf][my_rank][lrow] in owner CTA
    uint32_t r_ps[2] = {0, 0}, r_mbar[2] = {0, 0};
    if (!own) {
        r_ps[0]   = mapa_u32(smem_u32(&ps_in[0][rank][lrow]), owner);
        r_ps[1]   = mapa_u32(smem_u32(&ps_in[1][rank][lrow]), owner);
        r_mbar[0] = mapa_u32(smem_u32(&mbar[0]), owner);
        r_mbar[1] = mapa_u32(smem_u32(&mbar[1]), owner);
    }
    const uint32_t l_mbar[2] = { smem_u32(&mbar[0]), smem_u32(&mbar[1]) };

    int ph[2] = {0, 0};
    float xv = own ? (__ldg(xcol) + bias) : 0.f;   // x(0) + b_hh pre-folded

    for (int t = 0; t < Tn; ++t) {
        const int buf = t & 1;
        const int nb  = buf ^ 1;

        // prefetch next x (+bias fold, off critical path)
        float xnext = 0.f;
        if (own && (t + 1) < Tn) xnext = __ldg(xcol + (size_t)(t + 1) * Hn) + bias;

        // expect 3 sources x 64 rows x 4 B
        if (tid == 0) mbar_arrive_expect_tx(l_mbar[buf], 768);

        // 64-wide dot over owned h slice (32 FFMA2)
        const ulonglong2* hp = reinterpret_cast<const ulonglong2*>(hbuf[buf]);
        unsigned long long acc0 = 0ull, acc1 = 0ull;
#pragma unroll
        for (int i = 0; i < 16; i++) {
            ulonglong2 hv = hp[i];
            ffma2(acc0, w[2 * i],     hv.x);
            ffma2(acc1, w[2 * i + 1], hv.y);
        }
        float a0, a1, c0, c1;
        unpack2(acc0, a0, a1);
        unpack2(acc1, c0, c1);
        const float part = (a0 + c0) + (a1 + c1);

        if (!own) {
            // ship partial to the row's owner FIRST; drains in background
            st_async_f32(r_ps[buf], part, r_mbar[buf]);

            // head partials for h(t-1) — hidden under the owners' wait
            if (worker && t > 0) {
                const ulonglong2* hh = reinterpret_cast<const ulonglong2*>(&hbuf[buf][hq << 4]);
                unsigned long long b0 = 0ull, b1 = 0ull;
#pragma unroll
                for (int i = 0; i < 4; i++) {
                    ulonglong2 hv = hh[i];
                    ffma2(b0, wh[2 * i],     hv.x);
                    ffma2(b1, wh[2 * i + 1], hv.y);
                }
                float p0, p1, p2, p3;
                unpack2(b0, p0, p1);
                unpack2(b1, p2, p3);
                float hpv = (p0 + p2) + (p1 + p3);
                hpv += __shfl_xor_sync(0xffffffffu, hpv, 1);
                hpv += __shfl_xor_sync(0xffffffffu, hpv, 2);
                if (hq == 0) hp_base[(size_t)(t - 1) * (CL * 24)] = hpv;
            }
        } else {
            mbar_wait(l_mbar[buf], ph[buf]);
            ph[buf] ^= 1;
            // own slot is permanently 0 -> unconditional 4-way sum
            float s = part + xv
                    + ps_in[buf][0][lrow] + ps_in[buf][1][lrow]
                    + ps_in[buf][2][lrow] + ps_in[buf][3][lrow];
            float hn = tanh_approx(s);
            xv = xnext;
            hbuf[nb][lrow] = hn;
        }
        __syncthreads();
    }

    // final head partials for h(511) (in hbuf[0] after t=511 wrote nb=0)
    if (worker) {
        const ulonglong2* hh = reinterpret_cast<const ulonglong2*>(&hbuf[0][hq << 4]);
        unsigned long long b0 = 0ull, b1 = 0ull;
#pragma unroll
        for (int i = 0; i < 4; i++) {
            ulonglong2 hv = hh[i];
            ffma2(b0, wh[2 * i],     hv.x);
            ffma2(b1, wh[2 * i + 1], hv.y);
        }
        float p0, p1, p2, p3;
        unpack2(b0, p0, p1);
        unpack2(b1, p2, p3);
        float hpv = (p0 + p2) + (p1 + p3);
        hpv += __shfl_xor_sync(0xffffffffu, hpv, 1);
        hpv += __shfl_xor_sync(0xffffffffu, hpv, 2);
        if (hq == 0) hp_base[(size_t)(Tn - 1) * (CL * 24)] = hpv;
    }

    // keep smem/barriers alive until peers' in-flight st.asyncs complete
    asm volatile("barrier.cluster.arrive.aligned;" ::: "memory");
    asm volatile("barrier.cluster.wait.aligned;" ::: "memory");
}

// ---------------- kernel 3 (fused epilogue): mean + tridiagonal from g_hp ----------------
// One thread per (b, d, t): reduces the 4 rank-partials for mean / diag / off
// directly and writes mean + prec diagonal band. No g_bd intermediate.
__global__ void __launch_bounds__(256) k_epi(const float* __restrict__ b_mean,
                                             const float* __restrict__ b_bd,
                                             float* __restrict__ out_mean,
                                             float* __restrict__ prec) {
    const int idx = blockIdx.x * 256 + threadIdx.x;   // 0 .. Bn*Dn*Tn-1
    const int i   = idx & 511;                        // t
    const int bd_ = idx >> 9;                         // b*8 + d
    const int d   = bd_ & 7;
    const int b   = bd_ >> 3;
    const int bt  = b * Tn + i;

    const float* hp = g_hp + (size_t)bt * (CL * 24);

    // mean output
    float m = ((hp[d] + hp[24 + d]) + (hp[48 + d] + hp[72 + d])) + __ldg(b_mean + d);
    out_mean[(size_t)bt * Dn + d] = m;

    const float bb_diag = __ldg(b_bd + d);
    const float bb_off  = __ldg(b_bd + Dn + d);

    float diag_i = ((hp[8 + d] + hp[32 + d]) + (hp[56 + d] + hp[80 + d])) + bb_diag;
    float off_i  = ((hp[16 + d] + hp[40 + d]) + (hp[64 + d] + hp[88 + d])) + bb_off;

    float off_p = 0.f;
    if (i > 0) {
        const float* hq = hp - CL * 24;   // (b, t-1)
        off_p = ((hq[16 + d] + hq[40 + d]) + (hq[64 + d] + hq[88 + d])) + bb_off;
    }

    float mainv = diag_i * diag_i + off_p * off_p + EPSf;
    float supd  = diag_i * off_i;   // supd[i] (columns i/i+1)

    float* base = prec + ((size_t)bd_ * Tn + i) * Tn + i;   // [b,d,i,i]
    base[0] = mainv;
    if (i < Tn - 1) {
        base[1]  = supd;    // [i, i+1]
        base[Tn] = supd;    // [i+1, i]
    }
}

// ---------------- launch ----------------
extern "C" void kernel_launch(void* const* d_in, const int* in_sizes, int n_in,
                              void* d_out, int out_size) {
    const float* y      = (const float*)d_in[0];
    const float* W_ih   = (const float*)d_in[1];
    const float* W_hh   = (const float*)d_in[2];
    const float* b_ih   = (const float*)d_in[3];
    const float* b_hh   = (const float*)d_in[4];
    const float* W_mean = (const float*)d_in[5];
    const float* b_mean = (const float*)d_in[6];
    const float* W_bd   = (const float*)d_in[7];
    const float* b_bd   = (const float*)d_in[8];
    float* out = (float*)d_out;
    float* prec = out + Bn * Tn * Dn;

    k_xproj<<<dim3(Tn / 4, Bn), 256>>>(y, W_ih, b_ih);
    k_scan<<<GRID_SCAN, 256>>>(W_hh, b_hh, W_mean, W_bd, prec);  // scan + heads + zero-fill
    k_epi<<<(Bn * Dn * Tn) / 256, 256>>>(b_mean, b_bd, out, prec);
}

// round 16
// speedup vs baseline: 1.2291x; 1.1386x over previous
#include <cuda_runtime.h>
#include <cstdint>

#define Bn   16
#define Tn   512
#define INn  128
#define Hn   256
#define Dn   8
#define EPSf 1e-5f

#define CL        4            // CTAs per cluster (4-way k/row split) — measured optimum
#define SCAN_CTAS 64           // 16 batches x 4 CTAs
#define GRID_SCAN 256          // 64 scan CTAs + 192 zero-fill CTAs
#define TT        16           // time rows per xproj block

// ---------------- scratch (static device arrays; no allocation) ----------------
__device__ float g_xproj[Bn * Tn * Hn];          // 8 MB
__device__ float g_hp   [Bn * Tn * CL * 24];     // 3 MB: per-rank head partials

// ---------------- helpers ----------------
__device__ __forceinline__ uint32_t smem_u32(const void* p) {
    uint32_t a;
    asm("{ .reg .u64 t; cvta.to.shared.u64 t, %1; cvt.u32.u64 %0, t; }"
        : "=r"(a) : "l"(p));
    return a;
}

__device__ __forceinline__ uint32_t cluster_rank() {
    uint32_t r;
    asm("mov.u32 %0, %%cluster_ctarank;" : "=r"(r));
    return r;
}

__device__ __forceinline__ uint32_t mapa_u32(uint32_t local_addr, uint32_t rank) {
    uint32_t r;
    asm("mapa.shared::cluster.u32 %0, %1, %2;" : "=r"(r) : "r"(local_addr), "r"(rank));
    return r;
}

__device__ __forceinline__ unsigned long long pack2(float x, float y) {
    unsigned long long r;
    asm("mov.b64 %0, {%1, %2};" : "=l"(r) : "f"(x), "f"(y));
    return r;
}
__device__ __forceinline__ void unpack2(unsigned long long v, float& x, float& y) {
    asm("mov.b64 {%0, %1}, %2;" : "=f"(x), "=f"(y) : "l"(v));
}
// packed fp32x2 FMA (Blackwell FFMA2): 2 fp32 MACs per instruction
__device__ __forceinline__ void ffma2(unsigned long long& d,
                                      unsigned long long a,
                                      unsigned long long b) {
    asm("fma.rn.f32x2 %0, %1, %2, %3;" : "=l"(d) : "l"(a), "l"(b), "l"(d));
}

__device__ __forceinline__ float tanh_approx(float x) {
    float r;
    asm("tanh.approx.f32 %0, %1;" : "=f"(r) : "f"(x));
    return r;
}

__device__ __forceinline__ void mbar_init(uint32_t addr, uint32_t count) {
    asm volatile("mbarrier.init.shared.b64 [%0], %1;" :: "r"(addr), "r"(count) : "memory");
}

__device__ __forceinline__ void mbar_arrive_expect_tx(uint32_t addr, uint32_t bytes) {
    asm volatile("mbarrier.arrive.expect_tx.shared.b64 _, [%0], %1;"
                 :: "r"(addr), "r"(bytes) : "memory");
}

__device__ __forceinline__ void mbar_wait(uint32_t addr, int phase) {
    asm volatile(
        "{\n\t"
        ".reg .pred P1;\n\t"
        "LAB_%=:\n\t"
        "mbarrier.try_wait.parity.acquire.cta.shared::cta.b64 P1, [%0], %1, 0x989680;\n\t"
        "@P1 bra DONE_%=;\n\t"
        "bra LAB_%=;\n\t"
        "DONE_%=:\n\t"
        "}"
        :: "r"(addr), "r"(phase) : "memory");
}

// async remote smem store (b32) with tx-completion on the remote mbarrier
__device__ __forceinline__ void st_async_f32(uint32_t raddr, float v, uint32_t rmbar) {
    asm volatile(
        "st.async.shared::cluster.mbarrier::complete_tx::bytes.b32 [%0], %1, [%2];"
        :: "r"(raddr), "r"(__float_as_uint(v)), "r"(rmbar) : "memory");
}

// ---------------- kernel 1: x_proj = y @ W_ih^T + b_ih (register-W, smem-Y) ----------------
// Block: 256 threads (one per output channel h), TT=16 time rows, one batch.
// W row register-resident (loaded ONCE per block -> 4x less W traffic than before,
// no per-row L1 re-streaming). Y tile staged in smem; lanes broadcast-read it.
__global__ void __launch_bounds__(256, 1) k_xproj(const float* __restrict__ y,
                                                  const float* __restrict__ W_ih,
                                                  const float* __restrict__ b_ih) {
    __shared__ __align__(16) float ysm[TT * INn];   // 8 KB

    const int h  = threadIdx.x;       // 0..255
    const int b  = blockIdx.y;
    const int t0 = blockIdx.x * TT;

    // stage Y tile (TT*128 floats = 512 float4)
    {
        const float4* ysrc = reinterpret_cast<const float4*>(y + ((size_t)b * Tn + t0) * INn);
        float4* ydst = reinterpret_cast<float4*>(ysm);
        for (int i = h; i < TT * INn / 4; i += 256)
            ydst[i] = __ldg(ysrc + i);
    }

    // W row in registers: 64 f32x2
    unsigned long long w[64];
    {
        const float2* wr = reinterpret_cast<const float2*>(W_ih + h * INn);
#pragma unroll
        for (int i = 0; i < 64; i++) {
            float2 v = __ldg(wr + i);
            w[i] = pack2(v.x, v.y);
        }
    }
    __syncthreads();

    unsigned long long acc[TT];
#pragma unroll
    for (int tt = 0; tt < TT; tt++) acc[tt] = 0ull;

#pragma unroll
    for (int i = 0; i < 32; i++) {
#pragma unroll
        for (int tt = 0; tt < TT; tt++) {
            ulonglong2 yv = reinterpret_cast<const ulonglong2*>(ysm + tt * INn)[i];
            ffma2(acc[tt], w[2 * i],     yv.x);
            ffma2(acc[tt], w[2 * i + 1], yv.y);
        }
    }

    const float bias = __ldg(b_ih + h);
    size_t base = ((size_t)b * Tn + t0) * Hn + h;
#pragma unroll
    for (int tt = 0; tt < TT; tt++) {
        float x0, x1;
        unpack2(acc[tt], x0, x1);
        g_xproj[base + (size_t)tt * Hn] = (x0 + x1) + bias;
    }
}

// ---------------- kernel 2: RNN scan (EXACT R13) + in-scan head partials + prec zero-fill ----------------
__global__ void __cluster_dims__(CL, 1, 1) __launch_bounds__(256, 1)
k_scan(const float* __restrict__ W_hh, const float* __restrict__ b_hh,
       const float* __restrict__ W_mean, const float* __restrict__ W_bd,
       float* __restrict__ prec) {
    // ---- zero-fill CTAs ----
    if (blockIdx.x >= SCAN_CTAS) {
        const long long total = (long long)Bn * Dn * Tn * Tn / 4;   // float4 count
        const int nz = GRID_SCAN - SCAN_CTAS;
        long long i = (long long)(blockIdx.x - SCAN_CTAS) * blockDim.x + threadIdx.x;
        const long long stride = (long long)nz * blockDim.x;
        const float4 z = make_float4(0.f, 0.f, 0.f, 0.f);
        for (; i < total; i += stride)
            __stcs(reinterpret_cast<float4*>(prec) + i, z);
        return;
    }

    __shared__ __align__(16) float hbuf[2][64];      // this CTA's OWNED h slice
    __shared__ __align__(16) float ps_in[2][CL][64]; // incoming partials by source rank
    __shared__ __align__(8) unsigned long long mbar[2];

    const int tid = threadIdx.x;                 // = global output row
    const unsigned rank = cluster_rank();        // 0..3
    const int batch = blockIdx.x >> 2;
    const unsigned owner = (unsigned)tid >> 6;   // owner CTA of this row
    const bool own = (owner == rank);
    const int lrow = tid & 63;

    // register-resident weights: W_hh[tid, rank*64 .. +64)  (32 f32x2)
    unsigned long long w[32];
    {
        const float2* wr = reinterpret_cast<const float2*>(W_hh + (size_t)tid * Hn + (rank << 6));
#pragma unroll
        for (int i = 0; i < 32; i++) {
            float2 v = __ldg(wr + i);
            w[i] = pack2(v.x, v.y);
        }
    }
    const float bias = own ? __ldg(b_hh + tid) : 0.f;
    const float* xcol = g_xproj + (size_t)batch * Tn * Hn + tid;

    // ---- head-partial worker setup (96 shipper threads per CTA) ----
    const int sid = (tid >= (int)((rank << 6) + 64)) ? tid - 64 : tid;
    const bool worker = (!own) && (sid < 96);    // warp-aligned cutoff
    const int ho = sid >> 2;                     // head output 0..23 (8 mean + 16 bd)
    const int hq = sid & 3;                      // 16-wide k sub-quarter
    unsigned long long wh[8];
    if (worker) {
        const float* whrow = (ho < Dn ? W_mean + ho * Hn : W_bd + (ho - Dn) * Hn)
                             + (rank << 6) + (hq << 4);
        const float2* wh2 = reinterpret_cast<const float2*>(whrow);
#pragma unroll
        for (int i = 0; i < 8; i++) {
            float2 v = __ldg(wh2 + i);
            wh[i] = pack2(v.x, v.y);
        }
    }
    float* hp_base = g_hp + ((size_t)batch * Tn * CL + rank) * 24 + ho;

    if (tid == 0) { mbar_init(smem_u32(&mbar[0]), 1); mbar_init(smem_u32(&mbar[1]), 1); }
    if (tid < 64) { hbuf[0][tid] = 0.f; }                       // h(-1) = 0
    for (int i = tid; i < 2 * CL * 64; i += 256)                // zero ps_in (own slot stays 0)
        reinterpret_cast<float*>(ps_in)[i] = 0.f;
    __syncthreads();
    asm volatile("barrier.cluster.arrive.aligned;" ::: "memory");
    asm volatile("barrier.cluster.wait.aligned;" ::: "memory");

    // remote targets for shippers: slot [buf][my_rank][lrow] in owner CTA
    uint32_t r_ps[2] = {0, 0}, r_mbar[2] = {0, 0};
    if (!own) {
        r_ps[0]   = mapa_u32(smem_u32(&ps_in[0][rank][lrow]), owner);
        r_ps[1]   = mapa_u32(smem_u32(&ps_in[1][rank][lrow]), owner);
        r_mbar[0] = mapa_u32(smem_u32(&mbar[0]), owner);
        r_mbar[1] = mapa_u32(smem_u32(&mbar[1]), owner);
    }
    const uint32_t l_mbar[2] = { smem_u32(&mbar[0]), smem_u32(&mbar[1]) };

    int ph[2] = {0, 0};
    float xv = own ? __ldg(xcol) : 0.f;   // x for t=0

    for (int t = 0; t < Tn; ++t) {
        const int buf = t & 1;
        const int nb  = buf ^ 1;

        // prefetch next x (finalizer threads), latency hidden behind FMA
        float xnext = 0.f;
        if (own && (t + 1) < Tn) xnext = __ldg(xcol + (size_t)(t + 1) * Hn);

        // expect 3 sources x 64 rows x 4 B
        if (tid == 0) mbar_arrive_expect_tx(l_mbar[buf], 768);

        // 64-wide dot over owned h slice (32 FFMA2)
        const ulonglong2* hp = reinterpret_cast<const ulonglong2*>(hbuf[buf]);
        unsigned long long acc0 = 0ull, acc1 = 0ull;
#pragma unroll
        for (int i = 0; i < 16; i++) {
            ulonglong2 hv = hp[i];
            ffma2(acc0, w[2 * i],     hv.x);
            ffma2(acc1, w[2 * i + 1], hv.y);
        }
        float a0, a1, c0, c1;
        unpack2(acc0, a0, a1);
        unpack2(acc1, c0, c1);
        const float part = (a0 + c0) + (a1 + c1);

        if (!own) {
            // ship partial to the row's owner FIRST; drains in background
            st_async_f32(r_ps[buf], part, r_mbar[buf]);

            // head partials for h(t-1) — hidden under the owners' wait
            if (worker && t > 0) {
                const ulonglong2* hh = reinterpret_cast<const ulonglong2*>(&hbuf[buf][hq << 4]);
                unsigned long long b0 = 0ull, b1 = 0ull;
#pragma unroll
                for (int i = 0; i < 4; i++) {
                    ulonglong2 hv = hh[i];
                    ffma2(b0, wh[2 * i],     hv.x);
                    ffma2(b1, wh[2 * i + 1], hv.y);
                }
                float p0, p1, p2, p3;
                unpack2(b0, p0, p1);
                unpack2(b1, p2, p3);
                float hpv = (p0 + p2) + (p1 + p3);
                hpv += __shfl_xor_sync(0xffffffffu, hpv, 1);
                hpv += __shfl_xor_sync(0xffffffffu, hpv, 2);
                if (hq == 0) hp_base[(size_t)(t - 1) * (CL * 24)] = hpv;
            }
        } else {
            mbar_wait(l_mbar[buf], ph[buf]);
            ph[buf] ^= 1;
            // own slot is permanently 0 -> unconditional 4-way sum
            float s = part + xv + bias
                    + ps_in[buf][0][lrow] + ps_in[buf][1][lrow]
                    + ps_in[buf][2][lrow] + ps_in[buf][3][lrow];
            float hn = tanh_approx(s);
            xv = xnext;
            hbuf[nb][lrow] = hn;
        }
        __syncthreads();
    }

    // final head partials for h(511) (in hbuf[0] after t=511 wrote nb=0)
    if (worker) {
        const ulonglong2* hh = reinterpret_cast<const ulonglong2*>(&hbuf[0][hq << 4]);
        unsigned long long b0 = 0ull, b1 = 0ull;
#pragma unroll
        for (int i = 0; i < 4; i++) {
            ulonglong2 hv = hh[i];
            ffma2(b0, wh[2 * i],     hv.x);
            ffma2(b1, wh[2 * i + 1], hv.y);
        }
        float p0, p1, p2, p3;
        unpack2(b0, p0, p1);
        unpack2(b1, p2, p3);
        float hpv = (p0 + p2) + (p1 + p3);
        hpv += __shfl_xor_sync(0xffffffffu, hpv, 1);
        hpv += __shfl_xor_sync(0xffffffffu, hpv, 2);
        if (hq == 0) hp_base[(size_t)(Tn - 1) * (CL * 24)] = hpv;
    }

    // keep smem/barriers alive until peers' in-flight st.asyncs complete
    asm volatile("barrier.cluster.arrive.aligned;" ::: "memory");
    asm volatile("barrier.cluster.wait.aligned;" ::: "memory");
}

// ---------------- kernel 3 (fused epilogue): mean + tridiagonal from g_hp ----------------
__global__ void __launch_bounds__(256) k_epi(const float* __restrict__ b_mean,
                                             const float* __restrict__ b_bd,
                                             float* __restrict__ out_mean,
                                             float* __restrict__ prec) {
    const int idx = blockIdx.x * 256 + threadIdx.x;   // 0 .. Bn*Dn*Tn-1
    const int i   = idx & 511;                        // t
    const int bd_ = idx >> 9;                         // b*8 + d
    const int d   = bd_ & 7;
    const int b   = bd_ >> 3;
    const int bt  = b * Tn + i;

    const float* hp = g_hp + (size_t)bt * (CL * 24);

    // mean output
    float m = ((hp[d] + hp[24 + d]) + (hp[48 + d] + hp[72 + d])) + __ldg(b_mean + d);
    out_mean[(size_t)bt * Dn + d] = m;

    const float bb_diag = __ldg(b_bd + d);
    const float bb_off  = __ldg(b_bd + Dn + d);

    float diag_i = ((hp[8 + d] + hp[32 + d]) + (hp[56 + d] + hp[80 + d])) + bb_diag;
    float off_i  = ((hp[16 + d] + hp[40 + d]) + (hp[64 + d] + hp[88 + d])) + bb_off;

    float off_p = 0.f;
    if (i > 0) {
        const float* hq = hp - CL * 24;   // (b, t-1)
        off_p = ((hq[16 + d] + hq[40 + d]) + (hq[64 + d] + hq[88 + d])) + bb_off;
    }

    float mainv = diag_i * diag_i + off_p * off_p + EPSf;
    float supd  = diag_i * off_i;   // supd[i] (columns i/i+1)

    float* base = prec + ((size_t)bd_ * Tn + i) * Tn + i;   // [b,d,i,i]
    base[0] = mainv;
    if (i < Tn - 1) {
        base[1]  = supd;    // [i, i+1]
        base[Tn] = supd;    // [i+1, i]
    }
}

// ---------------- launch ----------------
extern "C" void kernel_launch(void* const* d_in, const int* in_sizes, int n_in,
                              void* d_out, int out_size) {
    const float* y      = (const float*)d_in[0];
    const float* W_ih   = (const float*)d_in[1];
    const float* W_hh   = (const float*)d_in[2];
    const float* b_ih   = (const float*)d_in[3];
    const float* b_hh   = (const float*)d_in[4];
    const float* W_mean = (const float*)d_in[5];
    const float* b_mean = (const float*)d_in[6];
    const float* W_bd   = (const float*)d_in[7];
    const float* b_bd   = (const float*)d_in[8];
    float* out = (float*)d_out;
    float* prec = out + Bn * Tn * Dn;

    k_xproj<<<dim3(Tn / TT, Bn), 256>>>(y, W_ih, b_ih);
    k_scan<<<GRID_SCAN, 256>>>(W_hh, b_hh, W_mean, W_bd, prec);  // scan + heads + zero-fill
    k_epi<<<(Bn * Dn * Tn) / 256, 256>>>(b_mean, b_bd, out, prec);
}

// round 17
// speedup vs baseline: 1.3627x; 1.1087x over previous
#include <cuda_runtime.h>
#include <cstdint>

#define Bn   16
#define Tn   512
#define INn  128
#define Hn   256
#define Dn   8
#define EPSf 1e-5f

#define CL        4            // CTAs per cluster (4-way k/row split) — measured optimum
#define SCAN_CTAS 64           // 16 batches x 4 CTAs
#define GRID_SCAN 256          // 64 scan CTAs + 192 zero-fill CTAs

// xproj GEMM tiles
#define XTM 64
#define XTN 64
#define XTK 32

// ---------------- scratch (static device arrays; no allocation) ----------------
__device__ float g_xproj[Bn * Tn * Hn];          // 8 MB
__device__ float g_hp   [Bn * Tn * CL * 24];     // 3 MB: per-rank head partials

// ---------------- helpers ----------------
__device__ __forceinline__ uint32_t smem_u32(const void* p) {
    uint32_t a;
    asm("{ .reg .u64 t; cvta.to.shared.u64 t, %1; cvt.u32.u64 %0, t; }"
        : "=r"(a) : "l"(p));
    return a;
}

__device__ __forceinline__ uint32_t cluster_rank() {
    uint32_t r;
    asm("mov.u32 %0, %%cluster_ctarank;" : "=r"(r));
    return r;
}

__device__ __forceinline__ uint32_t mapa_u32(uint32_t local_addr, uint32_t rank) {
    uint32_t r;
    asm("mapa.shared::cluster.u32 %0, %1, %2;" : "=r"(r) : "r"(local_addr), "r"(rank));
    return r;
}

__device__ __forceinline__ unsigned long long pack2(float x, float y) {
    unsigned long long r;
    asm("mov.b64 %0, {%1, %2};" : "=l"(r) : "f"(x), "f"(y));
    return r;
}
__device__ __forceinline__ void unpack2(unsigned long long v, float& x, float& y) {
    asm("mov.b64 {%0, %1}, %2;" : "=f"(x), "=f"(y) : "l"(v));
}
// packed fp32x2 FMA (Blackwell FFMA2): 2 fp32 MACs per instruction
__device__ __forceinline__ void ffma2(unsigned long long& d,
                                      unsigned long long a,
                                      unsigned long long b) {
    asm("fma.rn.f32x2 %0, %1, %2, %3;" : "=l"(d) : "l"(a), "l"(b), "l"(d));
}

__device__ __forceinline__ float tanh_approx(float x) {
    float r;
    asm("tanh.approx.f32 %0, %1;" : "=f"(r) : "f"(x));
    return r;
}

__device__ __forceinline__ void mbar_init(uint32_t addr, uint32_t count) {
    asm volatile("mbarrier.init.shared.b64 [%0], %1;" :: "r"(addr), "r"(count) : "memory");
}

__device__ __forceinline__ void mbar_arrive_expect_tx(uint32_t addr, uint32_t bytes) {
    asm volatile("mbarrier.arrive.expect_tx.shared.b64 _, [%0], %1;"
                 :: "r"(addr), "r"(bytes) : "memory");
}

__device__ __forceinline__ void mbar_wait(uint32_t addr, int phase) {
    asm volatile(
        "{\n\t"
        ".reg .pred P1;\n\t"
        "LAB_%=:\n\t"
        "mbarrier.try_wait.parity.acquire.cta.shared::cta.b64 P1, [%0], %1, 0x989680;\n\t"
        "@P1 bra DONE_%=;\n\t"
        "bra LAB_%=;\n\t"
        "DONE_%=:\n\t"
        "}"
        :: "r"(addr), "r"(phase) : "memory");
}

// async remote smem store (b32) with tx-completion on the remote mbarrier
__device__ __forceinline__ void st_async_f32(uint32_t raddr, float v, uint32_t rmbar) {
    asm volatile(
        "st.async.shared::cluster.mbarrier::complete_tx::bytes.b32 [%0], %1, [%2];"
        :: "r"(raddr), "r"(__float_as_uint(v)), "r"(rmbar) : "memory");
}

// ---------------- kernel 1: x_proj GEMM (64x64 tile, 4x4 register blocking) ----------------
// grid (Tn/64, Hn/64, Bn), 256 threads as 16x16. K staged transposed in smem.
__global__ void __launch_bounds__(256, 1) k_xproj(const float* __restrict__ y,
                                                  const float* __restrict__ W_ih,
                                                  const float* __restrict__ b_ih) {
    __shared__ __align__(16) float ys[XTK][XTM + 4];   // [k][t]
    __shared__ __align__(16) float ws[XTK][XTN + 4];   // [k][h]

    const int tx = threadIdx.x & 15;   // t-sub
    const int ty = threadIdx.x >> 4;   // h-sub
    const int t0 = blockIdx.x * XTM;
    const int h0 = blockIdx.y * XTN;
    const int b  = blockIdx.z;

    float acc[4][4] = {};

    for (int kc = 0; kc < INn; kc += XTK) {
        // cooperative load: 64 rows x 32 k (512 float4 each for y and W), transposed store
#pragma unroll
        for (int r = 0; r < 2; r++) {
            int idx  = threadIdx.x + r * 256;  // 0..511
            int row  = idx >> 3;               // 0..63
            int kg   = (idx & 7) << 2;         // 0,4,..28
            float4 v = __ldg(reinterpret_cast<const float4*>(
                y + ((size_t)b * Tn + t0 + row) * INn + kc + kg));
            ys[kg + 0][row] = v.x; ys[kg + 1][row] = v.y;
            ys[kg + 2][row] = v.z; ys[kg + 3][row] = v.w;
            float4 wv = __ldg(reinterpret_cast<const float4*>(
                W_ih + (size_t)(h0 + row) * INn + kc + kg));
            ws[kg + 0][row] = wv.x; ws[kg + 1][row] = wv.y;
            ws[kg + 2][row] = wv.z; ws[kg + 3][row] = wv.w;
        }
        __syncthreads();

#pragma unroll
        for (int k = 0; k < XTK; k++) {
            float4 yv = *reinterpret_cast<const float4*>(&ys[k][tx << 2]);
            float4 wv = *reinterpret_cast<const float4*>(&ws[k][ty << 2]);
            acc[0][0] += yv.x * wv.x; acc[0][1] += yv.x * wv.y;
            acc[0][2] += yv.x * wv.z; acc[0][3] += yv.x * wv.w;
            acc[1][0] += yv.y * wv.x; acc[1][1] += yv.y * wv.y;
            acc[1][2] += yv.y * wv.z; acc[1][3] += yv.y * wv.w;
            acc[2][0] += yv.z * wv.x; acc[2][1] += yv.z * wv.y;
            acc[2][2] += yv.z * wv.z; acc[2][3] += yv.z * wv.w;
            acc[3][0] += yv.w * wv.x; acc[3][1] += yv.w * wv.y;
            acc[3][2] += yv.w * wv.z; acc[3][3] += yv.w * wv.w;
        }
        __syncthreads();
    }

    const float4 bb = __ldg(reinterpret_cast<const float4*>(b_ih + h0 + (ty << 2)));
#pragma unroll
    for (int i = 0; i < 4; i++) {
        const int t = t0 + (tx << 2) + i;
        float4 o = make_float4(acc[i][0] + bb.x, acc[i][1] + bb.y,
                               acc[i][2] + bb.z, acc[i][3] + bb.w);
        *reinterpret_cast<float4*>(g_xproj + ((size_t)b * Tn + t) * Hn + h0 + (ty << 2)) = o;
    }
}

// ---------------- kernel 2: RNN scan (EXACT R13) + in-scan head partials + prec zero-fill ----------------
__global__ void __cluster_dims__(CL, 1, 1) __launch_bounds__(256, 1)
k_scan(const float* __restrict__ W_hh, const float* __restrict__ b_hh,
       const float* __restrict__ W_mean, const float* __restrict__ W_bd,
       float* __restrict__ prec) {
    // ---- zero-fill CTAs ----
    if (blockIdx.x >= SCAN_CTAS) {
        const long long total = (long long)Bn * Dn * Tn * Tn / 4;   // float4 count
        const int nz = GRID_SCAN - SCAN_CTAS;
        long long i = (long long)(blockIdx.x - SCAN_CTAS) * blockDim.x + threadIdx.x;
        const long long stride = (long long)nz * blockDim.x;
        const float4 z = make_float4(0.f, 0.f, 0.f, 0.f);
        for (; i < total; i += stride)
            __stcs(reinterpret_cast<float4*>(prec) + i, z);
        return;
    }

    __shared__ __align__(16) float hbuf[2][64];      // this CTA's OWNED h slice
    __shared__ __align__(16) float ps_in[2][CL][64]; // incoming partials by source rank
    __shared__ __align__(8) unsigned long long mbar[2];

    const int tid = threadIdx.x;                 // = global output row
    const unsigned rank = cluster_rank();        // 0..3
    const int batch = blockIdx.x >> 2;
    const unsigned owner = (unsigned)tid >> 6;   // owner CTA of this row
    const bool own = (owner == rank);
    const int lrow = tid & 63;

    // register-resident weights: W_hh[tid, rank*64 .. +64)  (32 f32x2)
    unsigned long long w[32];
    {
        const float2* wr = reinterpret_cast<const float2*>(W_hh + (size_t)tid * Hn + (rank << 6));
#pragma unroll
        for (int i = 0; i < 32; i++) {
            float2 v = __ldg(wr + i);
            w[i] = pack2(v.x, v.y);
        }
    }
    const float bias = own ? __ldg(b_hh + tid) : 0.f;
    const float* xcol = g_xproj + (size_t)batch * Tn * Hn + tid;

    // ---- head-partial worker setup (96 shipper threads per CTA) ----
    const int sid = (tid >= (int)((rank << 6) + 64)) ? tid - 64 : tid;
    const bool worker = (!own) && (sid < 96);    // warp-aligned cutoff
    const int ho = sid >> 2;                     // head output 0..23 (8 mean + 16 bd)
    const int hq = sid & 3;                      // 16-wide k sub-quarter
    unsigned long long wh[8];
    if (worker) {
        const float* whrow = (ho < Dn ? W_mean + ho * Hn : W_bd + (ho - Dn) * Hn)
                             + (rank << 6) + (hq << 4);
        const float2* wh2 = reinterpret_cast<const float2*>(whrow);
#pragma unroll
        for (int i = 0; i < 8; i++) {
            float2 v = __ldg(wh2 + i);
            wh[i] = pack2(v.x, v.y);
        }
    }
    float* hp_base = g_hp + ((size_t)batch * Tn * CL + rank) * 24 + ho;

    if (tid == 0) { mbar_init(smem_u32(&mbar[0]), 1); mbar_init(smem_u32(&mbar[1]), 1); }
    if (tid < 64) { hbuf[0][tid] = 0.f; }                       // h(-1) = 0
    for (int i = tid; i < 2 * CL * 64; i += 256)                // zero ps_in (own slot stays 0)
        reinterpret_cast<float*>(ps_in)[i] = 0.f;
    __syncthreads();
    asm volatile("barrier.cluster.arrive.aligned;" ::: "memory");
    asm volatile("barrier.cluster.wait.aligned;" ::: "memory");

    // remote targets for shippers: slot [buf][my_rank][lrow] in owner CTA
    uint32_t r_ps[2] = {0, 0}, r_mbar[2] = {0, 0};
    if (!own) {
        r_ps[0]   = mapa_u32(smem_u32(&ps_in[0][rank][lrow]), owner);
        r_ps[1]   = mapa_u32(smem_u32(&ps_in[1][rank][lrow]), owner);
        r_mbar[0] = mapa_u32(smem_u32(&mbar[0]), owner);
        r_mbar[1] = mapa_u32(smem_u32(&mbar[1]), owner);
    }
    const uint32_t l_mbar[2] = { smem_u32(&mbar[0]), smem_u32(&mbar[1]) };

    int ph[2] = {0, 0};
    float xv = own ? __ldg(xcol) : 0.f;   // x for t=0

    for (int t = 0; t < Tn; ++t) {
        const int buf = t & 1;
        const int nb  = buf ^ 1;

        // prefetch next x (finalizer threads), latency hidden behind FMA
        float xnext = 0.f;
        if (own && (t + 1) < Tn) xnext = __ldg(xcol + (size_t)(t + 1) * Hn);

        // expect 3 sources x 64 rows x 4 B
        if (tid == 0) mbar_arrive_expect_tx(l_mbar[buf], 768);

        // 64-wide dot over owned h slice (32 FFMA2)
        const ulonglong2* hp = reinterpret_cast<const ulonglong2*>(hbuf[buf]);
        unsigned long long acc0 = 0ull, acc1 = 0ull;
#pragma unroll
        for (int i = 0; i < 16; i++) {
            ulonglong2 hv = hp[i];
            ffma2(acc0, w[2 * i],     hv.x);
            ffma2(acc1, w[2 * i + 1], hv.y);
        }
        float a0, a1, c0, c1;
        unpack2(acc0, a0, a1);
        unpack2(acc1, c0, c1);
        const float part = (a0 + c0) + (a1 + c1);

        if (!own) {
            // ship partial to the row's owner FIRST; drains in background
            st_async_f32(r_ps[buf], part, r_mbar[buf]);

            // head partials for h(t-1) — hidden under the owners' wait
            if (worker && t > 0) {
                const ulonglong2* hh = reinterpret_cast<const ulonglong2*>(&hbuf[buf][hq << 4]);
                unsigned long long b0 = 0ull, b1 = 0ull;
#pragma unroll
                for (int i = 0; i < 4; i++) {
                    ulonglong2 hv = hh[i];
                    ffma2(b0, wh[2 * i],     hv.x);
                    ffma2(b1, wh[2 * i + 1], hv.y);
                }
                float p0, p1, p2, p3;
                unpack2(b0, p0, p1);
                unpack2(b1, p2, p3);
                float hpv = (p0 + p2) + (p1 + p3);
                hpv += __shfl_xor_sync(0xffffffffu, hpv, 1);
                hpv += __shfl_xor_sync(0xffffffffu, hpv, 2);
                if (hq == 0) hp_base[(size_t)(t - 1) * (CL * 24)] = hpv;
            }
        } else {
            mbar_wait(l_mbar[buf], ph[buf]);
            ph[buf] ^= 1;
            // own slot is permanently 0 -> unconditional 4-way sum
            float s = part + xv + bias
                    + ps_in[buf][0][lrow] + ps_in[buf][1][lrow]
                    + ps_in[buf][2][lrow] + ps_in[buf][3][lrow];
            float hn = tanh_approx(s);
            xv = xnext;
            hbuf[nb][lrow] = hn;
        }
        __syncthreads();
    }

    // final head partials for h(511) (in hbuf[0] after t=511 wrote nb=0)
    if (worker) {
        const ulonglong2* hh = reinterpret_cast<const ulonglong2*>(&hbuf[0][hq << 4]);
        unsigned long long b0 = 0ull, b1 = 0ull;
#pragma unroll
        for (int i = 0; i < 4; i++) {
            ulonglong2 hv = hh[i];
            ffma2(b0, wh[2 * i],     hv.x);
            ffma2(b1, wh[2 * i + 1], hv.y);
        }
        float p0, p1, p2, p3;
        unpack2(b0, p0, p1);
        unpack2(b1, p2, p3);
        float hpv = (p0 + p2) + (p1 + p3);
        hpv += __shfl_xor_sync(0xffffffffu, hpv, 1);
        hpv += __shfl_xor_sync(0xffffffffu, hpv, 2);
        if (hq == 0) hp_base[(size_t)(Tn - 1) * (CL * 24)] = hpv;
    }

    // keep smem/barriers alive until peers' in-flight st.asyncs complete
    asm volatile("barrier.cluster.arrive.aligned;" ::: "memory");
    asm volatile("barrier.cluster.wait.aligned;" ::: "memory");
}

// ---------------- kernel 3 (fused epilogue): mean + tridiagonal from g_hp ----------------
__global__ void __launch_bounds__(256) k_epi(const float* __restrict__ b_mean,
                                             const float* __restrict__ b_bd,
                                             float* __restrict__ out_mean,
                                             float* __restrict__ prec) {
    const int idx = blockIdx.x * 256 + threadIdx.x;   // 0 .. Bn*Dn*Tn-1
    const int i   = idx & 511;                        // t
    const int bd_ = idx >> 9;                         // b*8 + d
    const int d   = bd_ & 7;
    const int b   = bd_ >> 3;
    const int bt  = b * Tn + i;

    const float* hp = g_hp + (size_t)bt * (CL * 24);

    // mean output
    float m = ((hp[d] + hp[24 + d]) + (hp[48 + d] + hp[72 + d])) + __ldg(b_mean + d);
    out_mean[(size_t)bt * Dn + d] = m;

    const float bb_diag = __ldg(b_bd + d);
    const float bb_off  = __ldg(b_bd + Dn + d);

    float diag_i = ((hp[8 + d] + hp[32 + d]) + (hp[56 + d] + hp[80 + d])) + bb_diag;
    float off_i  = ((hp[16 + d] + hp[40 + d]) + (hp[64 + d] + hp[88 + d])) + bb_off;

    float off_p = 0.f;
    if (i > 0) {
        const float* hq = hp - CL * 24;   // (b, t-1)
        off_p = ((hq[16 + d] + hq[40 + d]) + (hq[64 + d] + hq[88 + d])) + bb_off;
    }

    float mainv = diag_i * diag_i + off_p * off_p + EPSf;
    float supd  = diag_i * off_i;   // supd[i] (columns i/i+1)

    float* base = prec + ((size_t)bd_ * Tn + i) * Tn + i;   // [b,d,i,i]
    base[0] = mainv;
    if (i < Tn - 1) {
        base[1]  = supd;    // [i, i+1]
        base[Tn] = supd;    // [i+1, i]
    }
}

// ---------------- launch ----------------
extern "C" void kernel_launch(void* const* d_in, const int* in_sizes, int n_in,
                              void* d_out, int out_size) {
    const float* y      = (const float*)d_in[0];
    const float* W_ih   = (const float*)d_in[1];
    const float* W_hh   = (const float*)d_in[2];
    const float* b_ih   = (const float*)d_in[3];
    const float* b_hh   = (const float*)d_in[4];
    const float* W_mean = (const float*)d_in[5];
    const float* b_mean = (const float*)d_in[6];
    const float* W_bd   = (const float*)d_in[7];
    const float* b_bd   = (const float*)d_in[8];
    float* out = (float*)d_out;
    float* prec = out + Bn * Tn * Dn;

    k_xproj<<<dim3(Tn / XTM, Hn / XTN, Bn), 256>>>(y, W_ih, b_ih);
    k_scan<<<GRID_SCAN, 256>>>(W_hh, b_hh, W_mean, W_bd, prec);  // scan + heads + zero-fill
    k_epi<<<(Bn * Dn * Tn) / 256, 256>>>(b_mean, b_bd, out, prec);
}